// round 6
// baseline (speedup 1.0000x reference)
#include <cuda_runtime.h>
#include <math.h>

#define T_TOK 512
#define DM    512
#define DE    1024
#define NE    64
#define NPAIR 1024
#define CHMAX 128

// ---------------- scratch (static device globals; no allocation) ----------------
__device__ float g_probs[T_TOK * NE];
__device__ int   g_topidx[NPAIR];
__device__ float g_topw[NPAIR];
__device__ int   g_rowTok[NPAIR];
__device__ float g_rowW[NPAIR];
__device__ int   g_cnt[NE];
__device__ int   g_off[NE];
__device__ int   g_chunkE[CHMAX], g_chunkB[CHMAX], g_chunkN[CHMAX];
__device__ int   g_nch;
__device__ float g_h[(size_t)NPAIR * DE];   // silu(gate)*up, [row][F], 4 MB

// ---------------- packed f32x2 FMA ----------------
__device__ __forceinline__ unsigned long long ffma2(unsigned long long a,
                                                    unsigned long long b,
                                                    unsigned long long c) {
    unsigned long long d;
    asm("fma.rn.f32x2 %0, %1, %2, %3;" : "=l"(d) : "l"(a), "l"(b), "l"(c));
    return d;
}
__device__ __forceinline__ float f2_sum(unsigned long long v) {
    return __uint_as_float((unsigned)v) + __uint_as_float((unsigned)(v >> 32));
}

__device__ __forceinline__ void cpa16(const void* smem_dst, const void* gsrc) {
    unsigned a = (unsigned)__cvta_generic_to_shared(smem_dst);
    asm volatile("cp.async.cg.shared.global [%0], [%1], 16;" :: "r"(a), "l"(gsrc));
}
__device__ __forceinline__ void cpa_commit() {
    asm volatile("cp.async.commit_group;" ::: "memory");
}
__device__ __forceinline__ void cpa_wait0() {
    asm volatile("cp.async.wait_group 0;" ::: "memory");
}

// ---------------- kernel 1: router (4 tokens per block) ----------------
__global__ __launch_bounds__(256) void router_kernel(const float* __restrict__ x,
                                                     const float* __restrict__ rw) {
    __shared__ float xs[4 * DM];
    __shared__ float lg[4 * NE];
    int tid = threadIdx.x, lane = tid & 31, warp = tid >> 5;
    int tbase = blockIdx.x * 4;

    for (int i = tid; i < 4 * DM / 4; i += 256)
        *(float4*)(xs + i * 4) = *(const float4*)(x + (size_t)tbase * DM + i * 4);
    __syncthreads();

    for (int j = 0; j < 8; j++) {
        int e = warp * 8 + j;
        const float* w = rw + (size_t)e * DM;
        float acc[4] = {0.f, 0.f, 0.f, 0.f};
        #pragma unroll
        for (int q = 0; q < 4; q++) {
            float4 wv = *(const float4*)(w + (size_t)(lane + 32 * q) * 4);
            int kb = (lane + 32 * q) * 4;
            #pragma unroll
            for (int t = 0; t < 4; t++) {
                acc[t] += wv.x * xs[t * DM + kb + 0];
                acc[t] += wv.y * xs[t * DM + kb + 1];
                acc[t] += wv.z * xs[t * DM + kb + 2];
                acc[t] += wv.w * xs[t * DM + kb + 3];
            }
        }
        #pragma unroll
        for (int t = 0; t < 4; t++) {
            float a = acc[t];
            #pragma unroll
            for (int off = 16; off; off >>= 1) a += __shfl_xor_sync(0xffffffffu, a, off);
            if (lane == 0) lg[t * NE + e] = a;
        }
    }
    __syncthreads();

    if (warp < 4) {
        int tl = warp;
        int t = tbase + tl;
        float l0 = lg[tl * NE + lane];
        float l1 = lg[tl * NE + lane + 32];
        float m = fmaxf(l0, l1);
        #pragma unroll
        for (int off = 16; off; off >>= 1) m = fmaxf(m, __shfl_xor_sync(0xffffffffu, m, off));
        float p0 = expf(l0 - m), p1 = expf(l1 - m);
        float s = p0 + p1;
        #pragma unroll
        for (int off = 16; off; off >>= 1) s += __shfl_xor_sync(0xffffffffu, s, off);
        g_probs[(size_t)t * NE + lane]      = p0 / s;
        g_probs[(size_t)t * NE + lane + 32] = p1 / s;

        float v; int ix;
        if (l1 > l0) { v = l1; ix = lane + 32; } else { v = l0; ix = lane; }
        #pragma unroll
        for (int off = 16; off; off >>= 1) {
            float ov = __shfl_xor_sync(0xffffffffu, v, off);
            int   oi = __shfl_xor_sync(0xffffffffu, ix, off);
            if (ov > v || (ov == v && oi < ix)) { v = ov; ix = oi; }
        }
        float v1 = v; int i1 = ix;
        float c0 = (lane == i1)      ? -INFINITY : l0;
        float c1 = (lane + 32 == i1) ? -INFINITY : l1;
        if (c1 > c0) { v = c1; ix = lane + 32; } else { v = c0; ix = lane; }
        #pragma unroll
        for (int off = 16; off; off >>= 1) {
            float ov = __shfl_xor_sync(0xffffffffu, v, off);
            int   oi = __shfl_xor_sync(0xffffffffu, ix, off);
            if (ov > v || (ov == v && oi < ix)) { v = ov; ix = oi; }
        }
        float v2 = v; int i2 = ix;
        if (lane == 0) {
            float q = expf(v2 - v1);
            g_topidx[2 * t]     = i1;
            g_topidx[2 * t + 1] = i2;
            g_topw[2 * t]       = 1.f / (1.f + q);
            g_topw[2 * t + 1]   = q / (1.f + q);
        }
    }
}

// ---------------- kernel 2: deterministic grouping + chunk table (1 block) ----------------
__global__ __launch_bounds__(1024) void group_kernel() {
    __shared__ int cnt_s[NE], off_s[NE];
    int tid = threadIdx.x, lane = tid & 31, warp = tid >> 5;

    for (int e = warp; e < NE; e += 32) {
        int c = 0;
        for (int ch = 0; ch < NPAIR / 32; ch++) {
            int a = g_topidx[ch * 32 + lane];
            unsigned mask = __ballot_sync(0xffffffffu, a == e);
            c += __popc(mask);
        }
        if (lane == 0) cnt_s[e] = c;
    }
    __syncthreads();
    if (tid == 0) {
        int r = 0, nc = 0;
        for (int e = 0; e < NE; e++) {
            off_s[e] = r;
            int n = cnt_s[e];
            for (int t0 = 0; t0 < n; t0 += 16) {
                g_chunkE[nc] = e;
                g_chunkB[nc] = r + t0;
                g_chunkN[nc] = min(16, n - t0);
                nc++;
            }
            r += n;
        }
        g_nch = nc;
    }
    __syncthreads();
    for (int e = warp; e < NE; e += 32) {
        int pos = off_s[e];
        for (int ch = 0; ch < NPAIR / 32; ch++) {
            int idx = ch * 32 + lane;
            int a = g_topidx[idx];
            unsigned mask = __ballot_sync(0xffffffffu, a == e);
            if (a == e) {
                int r = pos + __popc(mask & ((1u << lane) - 1u));
                g_rowTok[r] = idx;
                g_rowW[r]   = g_topw[idx];
            }
            pos += __popc(mask);
        }
    }
    if (tid < NE) { g_cnt[tid] = cnt_s[tid]; g_off[tid] = off_s[tid]; }
}

// ---------------- kernel 3: aux loss ----------------
__global__ __launch_bounds__(1024) void aux_kernel(float* auxp) {
    __shared__ float part[1024];
    int tid = threadIdx.x;
    int e = tid & 63, c = tid >> 6;
    float s = 0.f;
    int t0 = c * 32;
    for (int t = t0; t < t0 + 32; t++) s += g_probs[(size_t)t * NE + e];
    part[tid] = s;
    __syncthreads();
    if (tid < NE) {
        float tot = 0.f;
        for (int j = 0; j < 16; j++) tot += part[e + j * 64];
        part[tid] = tot * (64.0f / 512.0f);
    }
    __syncthreads();
    if (tid == 0 && auxp) {
        float m = 0.f;
        for (int i = 0; i < NE; i++) m += part[i];
        m *= (1.0f / 64.0f);
        float v = 0.f;
        for (int i = 0; i < NE; i++) { float d = part[i] - m; v += d * d; }
        auxp[0] = v * (1.0f / 63.0f);
    }
}

// ---------------- kernel 4: gate/up grouped GEMM -> h = silu(g)*u ----------------
// grid (8 ftiles of 128, CHMAX chunks), 128 thr (4 warps).
// lane: t4 = lane&3 (tokens t4+4i, i<4), fh = lane>>2 (0..7).
// thread f rows = warp*32 + fh + 8j (j<4), both matrices.
#define GU_KC 16
#define GU_ST (DM / GU_KC)   // 32 stages
__global__ __launch_bounds__(128, 4) void gateup_kernel(const float* __restrict__ x,
                                                        const float* __restrict__ wg,
                                                        const float* __restrict__ wu) {
    int c = blockIdx.y;
    if (c >= g_nch) return;
    int e     = g_chunkE[c];
    int rbase = g_chunkB[c];
    int cnt   = g_chunkN[c];
    int ft = blockIdx.x * 128;

    __shared__ __align__(16) float xs[2][16][20];
    __shared__ __align__(16) float ws[2][2][128][20];
    __shared__ int tok_s[16];

    int tid = threadIdx.x, lane = tid & 31, warp = tid >> 5;
    int t4 = lane & 3, fh = lane >> 2;
    int fbase = warp * 32 + fh;

    const float* wmat0 = wg + ((size_t)e * DE + ft) * DM;
    const float* wmat1 = wu + ((size_t)e * DE + ft) * DM;

    if (tid < 16) {
        int rr = min(tid, cnt - 1);
        tok_s[tid] = g_rowTok[rbase + rr] >> 1;
    }
    __syncthreads();

    int wp_mat[8], wp_r[8], wp_c[8];
    #pragma unroll
    for (int i = 0; i < 8; i++) {
        int p = i * 128 + tid;
        wp_mat[i] = p >> 9;
        int pm = p & 511;
        wp_r[i] = pm >> 2;
        wp_c[i] = (pm & 3) * 4;
    }
    int xr_ = tid >> 2, xc_ = (tid & 3) * 4;
    const float* myX = (tid < 64) ? (x + (size_t)tok_s[xr_] * DM + xc_) : x;

    unsigned long long ag[4][4], au[4][4];
    #pragma unroll
    for (int i = 0; i < 4; i++)
        #pragma unroll
        for (int j = 0; j < 4; j++) { ag[i][j] = 0ull; au[i][j] = 0ull; }

    auto loadStage = [&](int s, int bb) {
        int k0 = s * GU_KC;
        #pragma unroll
        for (int i = 0; i < 8; i++) {
            const float* src = (wp_mat[i] ? wmat1 : wmat0) + (size_t)wp_r[i] * DM + k0 + wp_c[i];
            cpa16(&ws[bb][wp_mat[i]][wp_r[i]][wp_c[i]], src);
        }
        if (tid < 64) cpa16(&xs[bb][xr_][xc_], myX + k0);
        cpa_commit();
    };

    loadStage(0, 0);
    for (int s = 0; s < GU_ST; s++) {
        cpa_wait0();
        __syncthreads();
        if (s + 1 < GU_ST) loadStage(s + 1, (s + 1) & 1);
        int bb = s & 1;
        #pragma unroll
        for (int q = 0; q < 4; q++) {
            ulonglong2 xv[4];
            #pragma unroll
            for (int i = 0; i < 4; i++)
                xv[i] = *(const ulonglong2*)&xs[bb][t4 + 4 * i][4 * q];
            #pragma unroll
            for (int j = 0; j < 4; j++) {
                ulonglong2 wgv = *(const ulonglong2*)&ws[bb][0][fbase + 8 * j][4 * q];
                ulonglong2 wuv = *(const ulonglong2*)&ws[bb][1][fbase + 8 * j][4 * q];
                #pragma unroll
                for (int i = 0; i < 4; i++) {
                    ag[i][j] = ffma2(wgv.x, xv[i].x, ag[i][j]);
                    ag[i][j] = ffma2(wgv.y, xv[i].y, ag[i][j]);
                    au[i][j] = ffma2(wuv.x, xv[i].x, au[i][j]);
                    au[i][j] = ffma2(wuv.y, xv[i].y, au[i][j]);
                }
            }
        }
    }

    #pragma unroll
    for (int i = 0; i < 4; i++) {
        int tt = t4 + 4 * i;
        if (tt < cnt) {
            int row = rbase + tt;
            float* hp = g_h + (size_t)row * DE + ft + fbase;
            #pragma unroll
            for (int j = 0; j < 4; j++) {
                float g = f2_sum(ag[i][j]);
                float u = f2_sum(au[i][j]);
                hp[8 * j] = (g / (1.f + expf(-g))) * u;
            }
        }
    }
}

// ---------------- kernel 5: down grouped GEMM + weighted scatter ----------------
// grid (8 = 2 dtiles x 4 k-splits, CHMAX chunks), 128 thr (4 warps).
// d-tile 256: warp covers 64 d rows; thread d rows = warp*64 + fh + 8j (j<8).
// Register tile: 4 tok x 8 d = 32 f32x2 accums. Split-K over DE in 4 spans of 256.
// out += wt * partial via atomicAdd (<=8 commutative contributions per element).
#define DN_KC 16
#define DN_SPLIT 4
#define DN_KSPAN (DE / DN_SPLIT)   // 256
#define DN_ST (DN_KSPAN / DN_KC)   // 16 stages
__global__ __launch_bounds__(128, 4) void down_kernel(const float* __restrict__ wd,
                                                      float* __restrict__ out) {
    int c = blockIdx.y;
    if (c >= g_nch) return;
    int e     = g_chunkE[c];
    int rbase = g_chunkB[c];
    int cnt   = g_chunkN[c];
    int dt    = (blockIdx.x >> 2) * 256;          // 0 or 256
    int kbase = (blockIdx.x & 3) * DN_KSPAN;      // 0,256,512,768

    __shared__ __align__(16) float hs[2][16][20];
    __shared__ __align__(16) float ws2[2][256][20];
    __shared__ int row_s[16];

    int tid = threadIdx.x, lane = tid & 31, warp = tid >> 5;
    int t4 = lane & 3, fh = lane >> 2;
    int dbase = warp * 64 + fh;

    const float* wdE = wd + ((size_t)e * DM + dt) * DE + kbase;

    if (tid < 16) row_s[tid] = rbase + min(tid, cnt - 1);
    __syncthreads();

    // weights: 256 rows x 4 float4 per stage = 1024 float4 / 128 thr = 8 each
    int wp_r[8], wp_c[8];
    #pragma unroll
    for (int i = 0; i < 8; i++) {
        int p = i * 128 + tid;
        wp_r[i] = p >> 2;          // 0..255
        wp_c[i] = (p & 3) * 4;
    }
    // h: 16 rows x 4 float4 = 64 -> tid<64
    int hr = tid >> 2, hc = (tid & 3) * 4;
    const float* myH = (tid < 64) ? (g_h + (size_t)row_s[hr] * DE + kbase + hc) : g_h;

    unsigned long long acc[4][8];
    #pragma unroll
    for (int i = 0; i < 4; i++)
        #pragma unroll
        for (int j = 0; j < 8; j++) acc[i][j] = 0ull;

    auto loadStage = [&](int s, int bb) {
        int k0 = s * DN_KC;
        #pragma unroll
        for (int i = 0; i < 8; i++)
            cpa16(&ws2[bb][wp_r[i]][wp_c[i]], wdE + (size_t)wp_r[i] * DE + k0 + wp_c[i]);
        if (tid < 64) cpa16(&hs[bb][hr][hc], myH + k0);
        cpa_commit();
    };

    loadStage(0, 0);
    for (int s = 0; s < DN_ST; s++) {
        cpa_wait0();
        __syncthreads();
        if (s + 1 < DN_ST) loadStage(s + 1, (s + 1) & 1);
        int bb = s & 1;
        #pragma unroll
        for (int q = 0; q < 4; q++) {
            ulonglong2 hv[4];
            #pragma unroll
            for (int i = 0; i < 4; i++)
                hv[i] = *(const ulonglong2*)&hs[bb][t4 + 4 * i][4 * q];
            #pragma unroll
            for (int j = 0; j < 8; j++) {
                ulonglong2 wv = *(const ulonglong2*)&ws2[bb][dbase + 8 * j][4 * q];
                #pragma unroll
                for (int i = 0; i < 4; i++) {
                    acc[i][j] = ffma2(wv.x, hv[i].x, acc[i][j]);
                    acc[i][j] = ffma2(wv.y, hv[i].y, acc[i][j]);
                }
            }
        }
    }

    #pragma unroll
    for (int i = 0; i < 4; i++) {
        int tt = t4 + 4 * i;
        if (tt < cnt) {
            int fidx = g_rowTok[rbase + tt];
            int tok = fidx >> 1;
            float wt = g_rowW[rbase + tt];
            float* op = out + (size_t)tok * DM + dt + dbase;
            #pragma unroll
            for (int j = 0; j < 8; j++)
                atomicAdd(op + 8 * j, wt * f2_sum(acc[i][j]));
        }
    }
}

// ---------------- launch ----------------
extern "C" void kernel_launch(void* const* d_in, const int* in_sizes, int n_in,
                              void* d_out, int out_size) {
    const float* x  = (const float*)d_in[0];
    const float* rw = (const float*)d_in[1];
    const float* wg = (const float*)d_in[2];
    const float* wu = (const float*)d_in[3];
    const float* wd = (const float*)d_in[4];
    float* out = (float*)d_out;

    cudaMemsetAsync(d_out, 0, (size_t)out_size * sizeof(float), 0);

    router_kernel<<<T_TOK / 4, 256>>>(x, rw);
    group_kernel<<<1, 1024>>>();

    float* auxp = (out_size > T_TOK * DM) ? out + (size_t)T_TOK * DM : nullptr;
    aux_kernel<<<1, 1024>>>(auxp);

    gateup_kernel<<<dim3(8, CHMAX), 128>>>(x, wg, wu);
    down_kernel<<<dim3(8, CHMAX), 128>>>(wd, out);
}